// round 16
// baseline (speedup 1.0000x reference)
#include <cuda_runtime.h>
#include <cstdint>

// GIKDWConv: depthwise 7x7 conv, stride 1, pad 3, 4-fold-rotation-symmetrized
// weights. N=16, C=384, H=W=64, fp32.
//
// R16: column-packed f32x2 + planar smem + 16-byte cp.async. Block = one
// (n, channel), 64x64 image as two pipelined 32-row halves (R12 structure).
// Planar float tile (38 rows x 72 floats; 4-float left pad aligns gmem col 0
// to 16B; halo columns always-zero via zfill chunks) makes loads 16B
// cp.async: 5.3 LDGSTS/thread/half instead of 41.6 (rt=8 each). Compute
// packs adjacent OUTPUT COLUMNS in f32x2: broadcast weight pairs, 5 aligned
// LDS.64 + 4 hi/lo merges build the 7 tap-pairs, factored C4 math (40 FFMA2
// + 3 FADD2 per row-iter per colpair) unchanged. 6144 uniform pipelined
// blocks also soften the wave tail (83% -> 92%).

#define HH 64
#define WW 64
#define NN 16
#define CC 384
#define TR 38              // tile rows: 32 output + 6 halo
#define TCF 72             // tile row stride in floats (16B-multiple)
#define CHUNKS 18          // 18 x 16B chunks per row (chunk0,17 = zero pads)
#define LCELLS (TR * CHUNKS)   // 684
#define NSL 6              // ceil(684/128) load slices
#define RPT 8              // output rows per thread
typedef unsigned long long ull;

__device__ constexpr int REP_I[13] = {0,0,0,0,0,0,1,1,1,1,2,2,3};
__device__ constexpr int REP_J[13] = {0,1,2,3,4,5,1,2,3,4,2,3,3};

// factored row formulas: per k, up to 6 (coef, src) terms.
// src indexes: 0=u06, 1..5 = s1..s5, 6=s0, 7=s6, 8=u15, 9=u24
__device__ constexpr int KNT[7]      = {6,6,6,4,6,6,6};
__device__ constexpr int KC[7][6] = {
    {0, 1, 2, 3, 4, 5},
    {6, 5, 7, 8, 9, 1},
    {10,4, 9, 11,7, 2},
    {3, 8, 11,12,0, 0},
    {10,2, 7, 11,9, 4},
    {6, 1, 9, 8, 7, 5},
    {0, 5, 4, 3, 2, 1}};
__device__ constexpr int KS[7][6] = {
    {0, 1, 2, 3, 4, 5},
    {8, 6, 2, 3, 4, 7},
    {9, 6, 1, 3, 5, 7},
    {0, 8, 9, 3, 0, 0},
    {9, 6, 1, 3, 5, 7},
    {8, 6, 2, 3, 4, 7},
    {0, 1, 2, 3, 4, 5}};

__device__ __forceinline__ ull fma2(ull a, ull b, ull c) {
    ull d;
    asm("fma.rn.f32x2 %0, %1, %2, %3;" : "=l"(d) : "l"(a), "l"(b), "l"(c));
    return d;
}
__device__ __forceinline__ ull add2(ull a, ull b) {
    ull d;
    asm("add.rn.f32x2 %0, %1, %2;" : "=l"(d) : "l"(a), "l"(b));
    return d;
}
__device__ __forceinline__ ull pack2(float lo, float hi) {
    ull r;
    asm("mov.b64 %0, {%1, %2};" : "=l"(r) : "f"(lo), "f"(hi));
    return r;
}
__device__ __forceinline__ void unpack2(ull v, float& lo, float& hi) {
    asm("mov.b64 {%0, %1}, %2;" : "=f"(lo), "=f"(hi) : "l"(v));
}
// (a.hi, b.lo): the misaligned middle pair of two aligned pairs
__device__ __forceinline__ ull mid2(ull a, ull b) {
    ull r;
    asm("{\n\t.reg .b32 t0, t1, t2, t3;\n\t"
        "mov.b64 {t0, t1}, %1;\n\t"
        "mov.b64 {t2, t3}, %2;\n\t"
        "mov.b64 %0, {t1, t2};\n\t}"
        : "=l"(r) : "l"(a), "l"(b));
    return r;
}
__device__ __forceinline__ uint32_t s2u(const void* p) {
    uint32_t a;
    asm("{ .reg .u64 t; cvta.to.shared.u64 t, %1; cvt.u32.u64 %0, t; }"
        : "=r"(a) : "l"(p));
    return a;
}
// 16-byte cp.async; sz=16 copies, sz=0 writes zeros (no src access)
__device__ __forceinline__ void cp16(uint32_t d, const float* s, int sz) {
    asm volatile("cp.async.cg.shared.global [%0], [%1], 16, %2;"
                 :: "r"(d), "l"(s), "r"(sz));
}

// incremental load cursor: thread's cell walks +128 per slice
// cell = r*18 + chunk; 128 = 7*18 + 2
struct PF {
    int r, ch;
    uint32_t dst;
    __device__ __forceinline__ void init(int tid, uint32_t base) {
        r = tid / CHUNKS;
        ch = tid - r * CHUNKS;
        dst = base + (uint32_t)tid * 16u;
    }
    __device__ __forceinline__ void advance() {
        ch += 2; r += 7;
        if (ch >= CHUNKS) { ch -= CHUNKS; r += 1; }
        dst += 128 * 16;
    }
    __device__ __forceinline__ void issue(const float* x0, int gy0) const {
        if (r < TR) {
            int gy = gy0 + r;
            int v = ((unsigned)gy < (unsigned)HH) & (ch >= 1) & (ch <= 16);
            const float* src = x0 + (v ? (gy * WW + (ch - 1) * 4) : 0);
            cp16(dst, src, v ? 16 : 0);
        }
    }
};

__global__ __launch_bounds__(128, 5)
void gik_dwconv_kernel(const float* __restrict__ x,
                       const float* __restrict__ weight,
                       float* __restrict__ out) {
    __shared__ float sxf[2][TR * TCF];  // planar half-tiles, 2 x 10.9 KB
    __shared__ ull sw[13];              // broadcast weight pairs (a,a)

    const int tid = threadIdx.x;
    const int c   = blockIdx.x;         // channel 0..383
    const int n   = blockIdx.y;         // batch 0..15

    const float* x0 = x + ((n * CC + c) * (HH * WW));
    const uint32_t sb0 = s2u(sxf[0]);
    const uint32_t sb1 = s2u(sxf[1]);

    // ---- prologue: load half 0 into buffer 0 ----
    {
        PF pf; pf.init(tid, sb0);
        #pragma unroll
        for (int s = 0; s < NSL; s++) { pf.issue(x0, -3); pf.advance(); }
        asm volatile("cp.async.commit_group;" ::: "memory");
    }

    // ---- the 13 unique symmetrized weights (broadcast pairs) ----
    if (tid < 13) {
        const int i = REP_I[tid], j = REP_J[tid];
        const float* w0 = weight + c * 49;
        float a = 0.25f * (w0[i*7 + j] + w0[j*7 + (6-i)] +
                           w0[(6-i)*7 + (6-j)] + w0[(6-j)*7 + i]);
        sw[tid] = pack2(a, a);
    }

    const int cx = (tid & 31) * 2;     // even output column 0..62
    const int r0 = (tid >> 5) * RPT;   // local output row base: 0,8,16,24

    asm volatile("cp.async.wait_group 0;" ::: "memory");
    __syncthreads();                   // half 0 + weights visible

    ull wreg[13];
    #pragma unroll
    for (int o = 0; o < 13; o++) wreg[o] = sw[o];

    PF pf; pf.init(tid, sb1);          // cursor for half-1 prefetch

    #pragma unroll
    for (int t = 0; t < 2; t++) {
        const float* sbf = sxf[t];

        ull acc[RPT];                  // packed (col cx, col cx+1)
        #pragma unroll
        for (int r = 0; r < RPT; r++) acc[r] = 0ull;

        #pragma unroll
        for (int y = 0; y < RPT + 6; y++) {
            // 5 aligned pairs covering gmem cols cx-4 .. cx+5
            // smem float index of gmem col j is j+4 -> base index = cx
            ull E[5];
            {
                const ull* ep =
                    (const ull*)(sbf + (r0 + y) * TCF + cx);
                #pragma unroll
                for (int q = 0; q < 5; q++) E[q] = ep[q];
            }
            // interleaved prefetch of half 1 (t=0): 1 slice/iter, y<6
            if (t == 0 && y < NSL) {
                pf.issue(x0, 29); pf.advance();
                if (y == NSL - 1)
                    asm volatile("cp.async.commit_group;" ::: "memory");
            }
            // tap pairs: s_t = (f[cx-3+t], f[cx-2+t])
            ull s0 = mid2(E[0], E[1]);
            ull s2 = mid2(E[1], E[2]);
            ull s4 = mid2(E[2], E[3]);
            ull s6 = mid2(E[3], E[4]);
            ull S[10];
            S[0] = add2(s0, s6);          // u06
            S[8] = add2(E[1], E[3]);      // u15 = s1 + s5
            S[9] = add2(s2, s4);          // u24
            S[1] = E[1]; S[2] = s2; S[3] = E[2]; S[4] = s4; S[5] = E[3];
            S[6] = s0;  S[7] = s6;

            #pragma unroll
            for (int k = 0; k < 7; k++) {
                const int r = y - k;
                if (r >= 0 && r < RPT) {
                    #pragma unroll
                    for (int u = 0; u < 6; u++) {
                        if (u < KNT[k])
                            acc[r] = fma2(wreg[KC[k][u]], S[KS[k][u]], acc[r]);
                    }
                }
            }
        }

        // ---- store: float2 per row (cols cx, cx+1 packed naturally) ----
        float* op = out + ((n * CC + c) * (HH * WW)) + t * 32 * WW;
        #pragma unroll
        for (int r = 0; r < RPT; r++) {
            float lo, hi;
            unpack2(acc[r], lo, hi);
            *(float2*)(op + (r0 + r) * WW + cx) = make_float2(lo, hi);
        }
        if (t == 0) {
            asm volatile("cp.async.wait_group 0;" ::: "memory");
            __syncthreads();           // half 1 fully resident in buffer 1
        }
    }
}

extern "C" void kernel_launch(void* const* d_in, const int* in_sizes, int n_in,
                              void* d_out, int out_size) {
    const float* x = (const float*)d_in[0];       // [16,384,64,64]
    const float* w = (const float*)d_in[1];       // [384,1,7,7]
    float* out = (float*)d_out;                   // [16,384,64,64]
    dim3 grid(CC, NN);
    gik_dwconv_kernel<<<grid, 128>>>(x, w, out);
}

// round 17
// speedup vs baseline: 1.1470x; 1.1470x over previous
#include <cuda_runtime.h>
#include <cstdint>

// GIKDWConv: depthwise 7x7 conv, stride 1, pad 3, 4-fold-rotation-symmetrized
// weights. N=16, C=384, H=W=64, fp32.
//
// R17: R15 (best: 52.8us) with the compute y-loop software-pipelined:
// per iteration, (1) pair-sums sA/sB are built from xv, (2) the NEXT row's
// 4 LDS.128 are issued into xv (dead after the sums), (3) the 40-FFMA2
// block runs, covering the 29-cycle LDS latency. Latency-bound per the
// warp-inst audit (pipe 58%, issue 51%, neither saturated). Everything
// else identical to R15: channel-pair f32x2, C4-factored filter, cp.async
// interleaved half pipeline, incremental loader cursor, 5 CTAs/SM.

#define HH 64
#define WW 64
#define NN 16
#define CC 384
#define TR 38              // tile rows: 32 output + 6 halo
#define TC 70              // tile cols: 64 output + 6 halo
#define CELLS (TR * TC)    // 2660
#define NSLICE 21          // ceil(2660/128)
#define RPT 8              // output rows per thread
typedef unsigned long long ull;

__device__ constexpr int REP_I[13] = {0,0,0,0,0,0,1,1,1,1,2,2,3};
__device__ constexpr int REP_J[13] = {0,1,2,3,4,5,1,2,3,4,2,3,3};

// factored row formulas: per k, up to 6 (coef, src) terms.
// src indexes: 0=u06, 1..5 = x1..x5, 6=x0, 7=x6, 8=u15, 9=u24
__device__ constexpr int KNT[7]      = {6,6,6,4,6,6,6};
__device__ constexpr int KC[7][6] = {
    {0, 1, 2, 3, 4, 5},
    {6, 5, 7, 8, 9, 1},
    {10,4, 9, 11,7, 2},
    {3, 8, 11,12,0, 0},
    {10,2, 7, 11,9, 4},
    {6, 1, 9, 8, 7, 5},
    {0, 5, 4, 3, 2, 1}};
__device__ constexpr int KS[7][6] = {
    {0, 1, 2, 3, 4, 5},
    {8, 6, 2, 3, 4, 7},
    {9, 6, 1, 3, 5, 7},
    {0, 8, 9, 3, 0, 0},
    {9, 6, 1, 3, 5, 7},
    {8, 6, 2, 3, 4, 7},
    {0, 1, 2, 3, 4, 5}};

__device__ __forceinline__ ull fma2(ull a, ull b, ull c) {
    ull d;
    asm("fma.rn.f32x2 %0, %1, %2, %3;" : "=l"(d) : "l"(a), "l"(b), "l"(c));
    return d;
}
__device__ __forceinline__ ull add2(ull a, ull b) {
    ull d;
    asm("add.rn.f32x2 %0, %1, %2;" : "=l"(d) : "l"(a), "l"(b));
    return d;
}
__device__ __forceinline__ ull pack2(float lo, float hi) {
    ull r;
    asm("mov.b64 %0, {%1, %2};" : "=l"(r) : "f"(lo), "f"(hi));
    return r;
}
__device__ __forceinline__ void unpack2(ull v, float& lo, float& hi) {
    asm("mov.b64 {%0, %1}, %2;" : "=f"(lo), "=f"(hi) : "l"(v));
}
__device__ __forceinline__ uint32_t s2u(const void* p) {
    uint32_t a;
    asm("{ .reg .u64 t; cvta.to.shared.u64 t, %1; cvt.u32.u64 %0, t; }"
        : "=r"(a) : "l"(p));
    return a;
}
// 4-byte cp.async with zfill: sz=4 copies, sz=0 writes zeros (no src access)
__device__ __forceinline__ void cp4(uint32_t d, const float* s, int sz) {
    asm volatile("cp.async.ca.shared.global [%0], [%1], 4, %2;"
                 :: "r"(d), "l"(s), "r"(sz));
}

// incremental slice cursor: this thread's cell walks +128 per slice
struct PF {
    int r, c;          // tile coords of this thread's cell
    uint32_t dst;      // smem address of that cell
    __device__ __forceinline__ void init(int tid, uint32_t base) {
        r = (tid >= TC) ? 1 : 0;
        c = tid - r * TC;
        dst = base + (uint32_t)tid * 8u;
    }
    __device__ __forceinline__ void advance() {
        c += 128 - TC; r += 1;
        if (c >= TC) { c -= TC; r += 1; }
        dst += 128 * 8;
    }
    __device__ __forceinline__ void issue(const float* x0, const float* x1,
                                          int gy0) const {
        if (r < TR) {
            int gy = gy0 + r, gx = c - 3;
            int v  = ((unsigned)gy < (unsigned)HH) &
                     ((unsigned)gx < (unsigned)WW);
            int off = v ? (gy * WW + gx) : 0;
            int sz  = v ? 4 : 0;
            cp4(dst,     x0 + off, sz);
            cp4(dst + 4, x1 + off, sz);
        }
    }
};

__device__ __forceinline__ void load_row(ull* xv, const ull* sb,
                                         int row, int cx) {
    const ulonglong2* rp = (const ulonglong2*)(sb + row * TC + cx);
    #pragma unroll
    for (int q = 0; q < 4; q++) {
        ulonglong2 v = rp[q];
        xv[2*q] = v.x; xv[2*q+1] = v.y;
    }
}

__global__ __launch_bounds__(128, 5)
void gik_dwconv_kernel(const float* __restrict__ x,
                       const float* __restrict__ weight,
                       float* __restrict__ out) {
    __shared__ ull sx[2 * CELLS];   // double-buffered packed half-tiles
    __shared__ ull sw[13];          // packed symmetric weights

    const int tid = threadIdx.x;
    const int cp  = blockIdx.x;         // channel pair 0..191
    const int n   = blockIdx.y;         // batch 0..15
    const int c0  = cp * 2;

    const float* x0 = x + ((n * CC + c0) * (HH * WW));
    const float* x1 = x0 + HH * WW;
    const uint32_t sbase = s2u(sx);

    // ---- prologue: load half 0 into buffer 0 (incremental cursor) ----
    {
        PF pf; pf.init(tid, sbase);
        #pragma unroll
        for (int s = 0; s < NSLICE; s++) {
            pf.issue(x0, x1, -3);
            pf.advance();
        }
        asm volatile("cp.async.commit_group;" ::: "memory");
    }

    // ---- the 13 unique symmetrized weights (LDG overlaps the cp.async) ----
    if (tid < 13) {
        const int i = REP_I[tid], j = REP_J[tid];
        const float* w0 = weight + c0 * 49;
        const float* w1 = w0 + 49;
        float a0 = 0.25f * (w0[i*7 + j] + w0[j*7 + (6-i)] +
                            w0[(6-i)*7 + (6-j)] + w0[(6-j)*7 + i]);
        float a1 = 0.25f * (w1[i*7 + j] + w1[j*7 + (6-i)] +
                            w1[(6-i)*7 + (6-j)] + w1[(6-j)*7 + i]);
        sw[tid] = pack2(a0, a1);
    }

    const int cx = (tid & 31) * 2;     // even output column 0..62
    const int r0 = (tid >> 5) * RPT;   // local output row base: 0,8,16,24

    asm volatile("cp.async.wait_group 0;" ::: "memory");
    __syncthreads();                   // half 0 + weights visible

    ull wreg[13];
    #pragma unroll
    for (int o = 0; o < 13; o++) wreg[o] = sw[o];

    PF pf; pf.init(tid, sbase + CELLS * 8);   // cursor for half-1 prefetch

    #pragma unroll
    for (int t = 0; t < 2; t++) {
        const ull* sb = sx + t * CELLS;

        ull acc0[RPT], acc1[RPT];      // col cx and cx+1
        #pragma unroll
        for (int r = 0; r < RPT; r++) { acc0[r] = 0ull; acc1[r] = 0ull; }

        ull xv[8];
        load_row(xv, sb, r0, cx);      // pipeline prologue: row 0

        #pragma unroll
        for (int y = 0; y < RPT + 6; y++) {
            // (1) pair-sums from xv — xv dead afterwards
            ull sA[10], sB[10];
            sA[0] = add2(xv[0], xv[6]);  sB[0] = add2(xv[1], xv[7]);  // u06
            sA[8] = add2(xv[1], xv[5]);  sB[8] = add2(xv[2], xv[6]);  // u15
            sA[9] = add2(xv[2], xv[4]);  sB[9] = add2(xv[3], xv[5]);  // u24
            sA[1]=xv[1]; sA[2]=xv[2]; sA[3]=xv[3]; sA[4]=xv[4];
            sA[5]=xv[5]; sA[6]=xv[0]; sA[7]=xv[6];
            sB[1]=xv[2]; sB[2]=xv[3]; sB[3]=xv[4]; sB[4]=xv[5];
            sB[5]=xv[6]; sB[6]=xv[1]; sB[7]=xv[7];

            // (2) issue next row's LDS now — latency hidden by (3)
            if (y < RPT + 5) load_row(xv, sb, r0 + y + 1, cx);

            // interleaved gmem prefetch of half 1 (t=0): 3 slices/iter, y<7
            if (t == 0 && y < 7) {
                pf.issue(x0, x1, 29); pf.advance();
                pf.issue(x0, x1, 29); pf.advance();
                pf.issue(x0, x1, 29); pf.advance();
            }

            // (3) the FMA block
            #pragma unroll
            for (int k = 0; k < 7; k++) {
                const int r = y - k;
                if (r >= 0 && r < RPT) {
                    #pragma unroll
                    for (int u = 0; u < 6; u++) {
                        if (u < KNT[k]) {
                            const ull w = wreg[KC[k][u]];
                            acc0[r] = fma2(w, sA[KS[k][u]], acc0[r]);
                            acc1[r] = fma2(w, sB[KS[k][u]], acc1[r]);
                        }
                    }
                }
            }
        }
        if (t == 0)
            asm volatile("cp.async.commit_group;" ::: "memory");

        // ---- store: float2 per channel-row ----
        float* o0 = out + ((n * CC + c0) * (HH * WW)) + t * 32 * WW;
        float* o1 = o0 + HH * WW;
        #pragma unroll
        for (int r = 0; r < RPT; r++) {
            float a, b, c, d;
            unpack2(acc0[r], a, b);     // a: c0 col cx,   b: c1 col cx
            unpack2(acc1[r], c, d);     // c: c0 col cx+1, d: c1 col cx+1
            const int off = (r0 + r) * WW + cx;
            *(float2*)(o0 + off) = make_float2(a, c);
            *(float2*)(o1 + off) = make_float2(b, d);
        }
        if (t == 0) {
            asm volatile("cp.async.wait_group 0;" ::: "memory");
            __syncthreads();           // half 1 fully resident in buffer 1
        }
    }
}

extern "C" void kernel_launch(void* const* d_in, const int* in_sizes, int n_in,
                              void* d_out, int out_size) {
    const float* x = (const float*)d_in[0];       // [16,384,64,64]
    const float* w = (const float*)d_in[1];       // [384,1,7,7]
    float* out = (float*)d_out;                   // [16,384,64,64]
    dim3 grid(CC / 2, NN);
    gik_dwconv_kernel<<<grid, 128>>>(x, w, out);
}